// round 4
// baseline (speedup 1.0000x reference)
#include <cuda_runtime.h>

// 2D Haar DWT, fp32, x:[16,64,512,512] -> out:[4,16,64,256,256]
// Pure streaming: 1 GiB in + 1 GiB out. DRAM-bound (R1: 87.7%, 6.95 TB/s).
// R4: persistent grid-stride version of R1. 65,536 short-lived CTAs (R1)
// showed achieved occ 75.6% vs theoretical 100% -> CTA drain/refill starves
// in-flight load count. 1184 resident CTAs loop over all tiles instead.
//
//   ll = 0.5*(a+b+c+d)   lh = 0.5*(a+b-c-d)
//   hl = 0.5*(a-b+c-d)   hh = 0.5*(a-b-c+d)

static constexpr int W_IN  = 512;
static constexpr int H_IN  = 512;
static constexpr int W_OUT = 256;
static constexpr int H_OUT = 256;
static constexpr int PLANES = 16 * 64;                                  // 1024
static constexpr long long OUT_PLANE = (long long)W_OUT * H_OUT;        // 65536
static constexpr long long BAND_STRIDE = (long long)PLANES * OUT_PLANE; // 67,108,864
static constexpr unsigned TOTAL = (unsigned)PLANES * H_OUT * (W_OUT / 4); // 16,777,216

static constexpr int NBLOCKS = 148 * 8;   // one full wave of 8 CTAs/SM

__global__ __launch_bounds__(256, 8) void haar_dwt_kernel(
    const float* __restrict__ x, float* __restrict__ out)
{
    const unsigned step = NBLOCKS * 256u;
    for (unsigned idx = blockIdx.x * 256u + threadIdx.x; idx < TOTAL; idx += step) {
        unsigned tx = idx & 63u;          // 4-col group within row
        unsigned h  = (idx >> 6) & 255u;  // output row
        unsigned p  = idx >> 14;          // plane 0..1023

        const float* base = x + (size_t)p * (W_IN * H_IN)
                              + (size_t)(2u * h) * W_IN + tx * 8u;
        float4 r0a = *reinterpret_cast<const float4*>(base);
        float4 r0b = *reinterpret_cast<const float4*>(base + 4);
        float4 r1a = *reinterpret_cast<const float4*>(base + W_IN);
        float4 r1b = *reinterpret_cast<const float4*>(base + W_IN + 4);

        float4 ll, lh, hl, hh;
        {
            float sT = r0a.x + r0a.y, dT = r0a.x - r0a.y;
            float sB = r1a.x + r1a.y, dB = r1a.x - r1a.y;
            ll.x = 0.5f * (sT + sB); lh.x = 0.5f * (sT - sB);
            hl.x = 0.5f * (dT + dB); hh.x = 0.5f * (dT - dB);
        }
        {
            float sT = r0a.z + r0a.w, dT = r0a.z - r0a.w;
            float sB = r1a.z + r1a.w, dB = r1a.z - r1a.w;
            ll.y = 0.5f * (sT + sB); lh.y = 0.5f * (sT - sB);
            hl.y = 0.5f * (dT + dB); hh.y = 0.5f * (dT - dB);
        }
        {
            float sT = r0b.x + r0b.y, dT = r0b.x - r0b.y;
            float sB = r1b.x + r1b.y, dB = r1b.x - r1b.y;
            ll.z = 0.5f * (sT + sB); lh.z = 0.5f * (sT - sB);
            hl.z = 0.5f * (dT + dB); hh.z = 0.5f * (dT - dB);
        }
        {
            float sT = r0b.z + r0b.w, dT = r0b.z - r0b.w;
            float sB = r1b.z + r1b.w, dB = r1b.z - r1b.w;
            ll.w = 0.5f * (sT + sB); lh.w = 0.5f * (sT - sB);
            hl.w = 0.5f * (dT + dB); hh.w = 0.5f * (dT - dB);
        }

        float* o = out + (size_t)p * OUT_PLANE + (size_t)h * W_OUT + tx * 4u;
        *reinterpret_cast<float4*>(o)                   = ll;
        *reinterpret_cast<float4*>(o + BAND_STRIDE)     = lh;
        *reinterpret_cast<float4*>(o + 2 * BAND_STRIDE) = hl;
        *reinterpret_cast<float4*>(o + 3 * BAND_STRIDE) = hh;
    }
}

extern "C" void kernel_launch(void* const* d_in, const int* in_sizes, int n_in,
                              void* d_out, int out_size) {
    const float* x = (const float*)d_in[0];
    float* out = (float*)d_out;
    haar_dwt_kernel<<<NBLOCKS, 256>>>(x, out);
}

// round 5
// speedup vs baseline: 1.0300x; 1.0300x over previous
#include <cuda_runtime.h>

// 2D Haar DWT, fp32, x:[16,64,512,512] -> out:[4,16,64,256,256]
// Pure streaming, DRAM-bound. Best so far: R1 one-shot grid, 308us, 87% HBM.
// R4 (persistent, unpipelined) regressed: per-warp load-issue gaps.
// R5: persistent + SOFTWARE PIPELINED — prefetch tile i+1's loads before
// compute/store of tile i. 2 output cols/thread keeps double-buffer regs ~32
// (8 CTAs/SM). Loads fully dense LDG.128 (512B/warp/instr).
//
//   ll = 0.5*(a+b+c+d)   lh = 0.5*(a+b-c-d)
//   hl = 0.5*(a-b+c-d)   hh = 0.5*(a-b-c+d)

static constexpr int W_IN  = 512;
static constexpr int W_OUT = 256;
static constexpr int H_OUT = 256;
static constexpr int PLANES = 16 * 64;                                  // 1024
static constexpr long long IN_PLANE  = (long long)W_IN * 512;           // 262144
static constexpr long long OUT_PLANE = (long long)W_OUT * H_OUT;        // 65536
static constexpr long long BAND_STRIDE = (long long)PLANES * OUT_PLANE; // 67,108,864
// one item = 2 output cols -> 128 groups/row
static constexpr unsigned TOTAL = (unsigned)PLANES * H_OUT * (W_OUT / 2); // 33,554,432

static constexpr int NBLOCKS = 148 * 8;   // 1184 CTAs, 8/SM

__device__ __forceinline__ const float* in_addr(const float* x, unsigned idx) {
    unsigned tx = idx & 127u;           // 2-col group (input cols 4tx..4tx+3)
    unsigned h  = (idx >> 7) & 255u;    // output row
    unsigned p  = idx >> 15;            // plane
    return x + (size_t)p * IN_PLANE + (size_t)(2u * h) * W_IN + tx * 4u;
}

__global__ __launch_bounds__(256, 8) void haar_dwt_kernel(
    const float* __restrict__ x, float* __restrict__ out)
{
    const unsigned step = NBLOCKS * 256u;          // 303,104
    unsigned idx = blockIdx.x * 256u + threadIdx.x;

    // Prologue: load tile(idx). (TOTAL > step, so idx < TOTAL always here.)
    const float* b0 = in_addr(x, idx);
    float4 c0 = *reinterpret_cast<const float4*>(b0);
    float4 c1 = *reinterpret_cast<const float4*>(b0 + W_IN);

    while (true) {
        unsigned nidx = idx + step;

        // Prefetch next tile BEFORE touching current data — its latency
        // overlaps current compute + stores.
        float4 n0 = c0, n1 = c1;
        if (nidx < TOTAL) {
            const float* bn = in_addr(x, nidx);
            n0 = *reinterpret_cast<const float4*>(bn);
            n1 = *reinterpret_cast<const float4*>(bn + W_IN);
        }

        // Compute current tile: 2 output cols from 2x4 input block.
        float2 ll, lh, hl, hh;
        {
            float sT = c0.x + c0.y, dT = c0.x - c0.y;
            float sB = c1.x + c1.y, dB = c1.x - c1.y;
            ll.x = 0.5f * (sT + sB); lh.x = 0.5f * (sT - sB);
            hl.x = 0.5f * (dT + dB); hh.x = 0.5f * (dT - dB);
        }
        {
            float sT = c0.z + c0.w, dT = c0.z - c0.w;
            float sB = c1.z + c1.w, dB = c1.z - c1.w;
            ll.y = 0.5f * (sT + sB); lh.y = 0.5f * (sT - sB);
            hl.y = 0.5f * (dT + dB); hh.y = 0.5f * (dT - dB);
        }

        {
            unsigned tx = idx & 127u;
            unsigned h  = (idx >> 7) & 255u;
            unsigned p  = idx >> 15;
            float* o = out + (size_t)p * OUT_PLANE + (size_t)h * W_OUT + tx * 2u;
            *reinterpret_cast<float2*>(o)                   = ll;
            *reinterpret_cast<float2*>(o + BAND_STRIDE)     = lh;
            *reinterpret_cast<float2*>(o + 2 * BAND_STRIDE) = hl;
            *reinterpret_cast<float2*>(o + 3 * BAND_STRIDE) = hh;
        }

        if (nidx >= TOTAL) break;
        c0 = n0; c1 = n1;
        idx = nidx;
    }
}

extern "C" void kernel_launch(void* const* d_in, const int* in_sizes, int n_in,
                              void* d_out, int out_size) {
    const float* x = (const float*)d_in[0];
    float* out = (float*)d_out;
    haar_dwt_kernel<<<NBLOCKS, 256>>>(x, out);
}

// round 6
// speedup vs baseline: 1.1269x; 1.0940x over previous
#include <cuda_runtime.h>

// 2D Haar DWT, fp32, x:[16,64,512,512] -> out:[4,16,64,256,256]
// Pure streaming, DRAM-bound. Best: R1 one-shot grid (308us, 87.7% DRAM).
// Persistent variants (R4/R5) plateau at 80% DRAM regardless of occupancy ->
// one-shot CTA drain/refill IS the pipeline. Keep it.
// R6: one-shot grid + DENSE per-thread loads — 2 output cols/thread, each
// lane loads 16B at 16B stride (R1 loaded 16B at 32B stride = half-sector
// accesses paired through L1). One fully dense 512B warp access per LDG.128,
// fewer L1tex wavefronts, lower regs -> more CTAs in flight.
//
//   ll = 0.5*(a+b+c+d)   lh = 0.5*(a+b-c-d)
//   hl = 0.5*(a-b+c-d)   hh = 0.5*(a-b-c+d)

static constexpr int W_IN  = 512;
static constexpr int W_OUT = 256;
static constexpr int H_OUT = 256;
static constexpr int PLANES = 16 * 64;                                  // 1024
static constexpr long long IN_PLANE  = (long long)W_IN * 512;           // 262144
static constexpr long long OUT_PLANE = (long long)W_OUT * H_OUT;        // 65536
static constexpr long long BAND_STRIDE = (long long)PLANES * OUT_PLANE; // 67,108,864

__global__ __launch_bounds__(256) void haar_dwt_kernel(
    const float* __restrict__ x, float* __restrict__ out)
{
    unsigned idx = blockIdx.x * 256u + threadIdx.x;   // 0 .. 33,554,431
    unsigned tx = idx & 127u;          // 2-col group (input cols 4tx..4tx+3)
    unsigned h  = (idx >> 7) & 255u;   // output row
    unsigned p  = idx >> 15;           // plane 0..1023

    // Dense: thread loads 4 consecutive floats (16B) from each of rows 2h, 2h+1.
    const float* base = x + (size_t)p * IN_PLANE + (size_t)(2u * h) * W_IN + tx * 4u;
    float4 c0 = *reinterpret_cast<const float4*>(base);
    float4 c1 = *reinterpret_cast<const float4*>(base + W_IN);

    float2 ll, lh, hl, hh;
    {
        float sT = c0.x + c0.y, dT = c0.x - c0.y;
        float sB = c1.x + c1.y, dB = c1.x - c1.y;
        ll.x = 0.5f * (sT + sB); lh.x = 0.5f * (sT - sB);
        hl.x = 0.5f * (dT + dB); hh.x = 0.5f * (dT - dB);
    }
    {
        float sT = c0.z + c0.w, dT = c0.z - c0.w;
        float sB = c1.z + c1.w, dB = c1.z - c1.w;
        ll.y = 0.5f * (sT + sB); lh.y = 0.5f * (sT - sB);
        hl.y = 0.5f * (dT + dB); hh.y = 0.5f * (dT - dB);
    }

    float* o = out + (size_t)p * OUT_PLANE + (size_t)h * W_OUT + tx * 2u;
    *reinterpret_cast<float2*>(o)                   = ll;
    *reinterpret_cast<float2*>(o + BAND_STRIDE)     = lh;
    *reinterpret_cast<float2*>(o + 2 * BAND_STRIDE) = hl;
    *reinterpret_cast<float2*>(o + 3 * BAND_STRIDE) = hh;
}

extern "C" void kernel_launch(void* const* d_in, const int* in_sizes, int n_in,
                              void* d_out, int out_size) {
    const float* x = (const float*)d_in[0];
    float* out = (float*)d_out;
    // total threads = 1024 planes * 256 rows * 128 groups = 33,554,432
    unsigned total = (unsigned)PLANES * H_OUT * (W_OUT / 2);
    haar_dwt_kernel<<<total / 256, 256>>>(x, out);
}